// round 8
// baseline (speedup 1.0000x reference)
#include <cuda_runtime.h>
#include <cuda_bf16.h>

#define FULL_MASK 0xFFFFFFFFu

// gram index for (i,j), i<=j, nv=5 -> linear index in s[15]
__device__ __forceinline__ constexpr int sidx(int i, int j) {
    return (i == 0 ? 0 : i == 1 ? 5 : i == 2 ? 9 : i == 3 ? 12 : 14) + (j - i);
}

// pair index for (i,j), i<j, nv=5 -> 0..9 in reference order
__device__ __forceinline__ constexpr int pidx(int i, int j) {
    return (i == 0 ? 0 : i == 1 ? 3 : i == 2 ? 5 : 6) + (j - 1);
}

__device__ __forceinline__ void load_quad(float4 v[5][4],
                                          const float4* __restrict__ base,
                                          int quad, int grp, int sub) {
    // quad covers batches [quad*4, quad*4+4); this lane's batch = quad*4+grp.
    const float4* vp = base + ((size_t)quad * 4 + grp) * 160 + sub;
#pragma unroll
    for (int i = 0; i < 5; i++) {
#pragma unroll
        for (int c = 0; c < 4; c++) {
            v[i][c] = __ldcs(vp + i * 32 + c * 8);
        }
    }
}

__global__ void __launch_bounds__(256, 2)
cm_validator_kernel(const float* __restrict__ verts,
                    float* __restrict__ out_pairs,   // (B, 10)
                    float* __restrict__ out_vol,     // (B,)
                    int B)
{
    const int nwarps = gridDim.x * (blockDim.x >> 5);
    const int warp = blockIdx.x * (blockDim.x >> 5) + (threadIdx.x >> 5);
    const int lane = threadIdx.x & 31;
    const int grp  = lane >> 3;        // 4 batches per warp-quad
    const int sub  = lane & 7;         // 8 lanes x 16 dims per batch

    const int nquads = (B + 3) >> 2;   // B is a multiple of 4 in practice
    const float4* base = reinterpret_cast<const float4*>(verts);

    if (warp >= nquads) return;

    float4 v[5][4];
    load_quad(v, base, warp, grp, sub);

    for (int quad = warp; quad < nquads; quad += nwarps) {
        const int batch = quad * 4 + grp;

        // ---- 15 partial dot products over this lane's 16 dims (v dies here)
        float s[15];
        {
            int t = 0;
#pragma unroll
            for (int i = 0; i < 5; i++) {
#pragma unroll
                for (int j = i; j < 5; j++) {
                    float acc = v[i][0].x * v[j][0].x;
#pragma unroll
                    for (int c = 0; c < 4; c++) {
                        if (c > 0) acc = fmaf(v[i][c].x, v[j][c].x, acc);
                        acc = fmaf(v[i][c].y, v[j][c].y, acc);
                        acc = fmaf(v[i][c].z, v[j][c].z, acc);
                        acc = fmaf(v[i][c].w, v[j][c].w, acc);
                    }
                    s[t++] = acc;
                }
            }
        }

        // ---- prefetch next quad NOW; loads overlap the epilogue below.
        const int nextq = quad + nwarps;
        const bool has_next = nextq < nquads;
        float4 vn[5][4];
        if (has_next) {
            load_quad(vn, base, nextq, grp, sub);
        }

        // ---- butterfly all-reduce within each 8-lane group: 3 x 15 shfl.
#pragma unroll
        for (int m = 4; m > 0; m >>= 1) {
#pragma unroll
            for (int p = 0; p < 15; p++) {
                s[p] += __shfl_xor_sync(FULL_MASK, s[p], m);
            }
        }

        // ---- squared distances for the 10 pairs, reference order.
        float nrm[5] = {s[sidx(0,0)], s[sidx(1,1)], s[sidx(2,2)],
                        s[sidx(3,3)], s[sidx(4,4)]};

        float d2[10];
#pragma unroll
        for (int i = 0; i < 5; i++) {
#pragma unroll
            for (int j = i + 1; j < 5; j++) {
                const float g = s[sidx(i, j)];
                d2[pidx(i, j)] = fmaxf(fmaf(-2.0f, g, nrm[i] + nrm[j]), 0.0f);
            }
        }

        // ---- Cayley-Menger det reduced exactly (two unit-pivot eliminations)
        // to a symmetric 4x4: vol2 = det(P) / 9216.
        const float p00 = -2.0f * d2[pidx(0,1)];
        const float p11 = -2.0f * d2[pidx(0,2)];
        const float p22 = -2.0f * d2[pidx(0,3)];
        const float p33 = -2.0f * d2[pidx(0,4)];
        const float p01 = d2[pidx(1,2)] - d2[pidx(0,2)] - d2[pidx(0,1)];
        const float p02 = d2[pidx(1,3)] - d2[pidx(0,3)] - d2[pidx(0,1)];
        const float p03 = d2[pidx(1,4)] - d2[pidx(0,4)] - d2[pidx(0,1)];
        const float p12 = d2[pidx(2,3)] - d2[pidx(0,3)] - d2[pidx(0,2)];
        const float p13 = d2[pidx(2,4)] - d2[pidx(0,4)] - d2[pidx(0,2)];
        const float p23 = d2[pidx(3,4)] - d2[pidx(0,4)] - d2[pidx(0,3)];

        const float s0 = p00 * p11 - p01 * p01;
        const float s1 = p00 * p12 - p02 * p01;
        const float s2 = p00 * p13 - p03 * p01;
        const float s3 = p01 * p12 - p02 * p11;
        const float s4 = p01 * p13 - p03 * p11;
        const float s5 = p02 * p13 - p03 * p12;

        const float c1 = p02 * p23 - p22 * p03;
        const float c2 = p02 * p33 - p23 * p03;
        const float c3 = p12 * p23 - p22 * p13;
        const float c4 = p12 * p33 - p23 * p13;
        const float c5 = p22 * p33 - p23 * p23;

        const float det4 = s0 * c5 - s1 * c4 + s2 * c3 + s3 * c2 - s4 * c1 + s5 * s5;
        const float vol2 = det4 * (1.0f / 9216.0f);

        // ---- outputs: lanes sub=0..7 own pairs 0..7; sub=0,1 also write 8,9.
        float pv = d2[0];
        pv = (sub == 1) ? d2[1] : pv;
        pv = (sub == 2) ? d2[2] : pv;
        pv = (sub == 3) ? d2[3] : pv;
        pv = (sub == 4) ? d2[4] : pv;
        pv = (sub == 5) ? d2[5] : pv;
        pv = (sub == 6) ? d2[6] : pv;
        pv = (sub == 7) ? d2[7] : pv;
        const float pv2 = (sub == 0) ? d2[8] : d2[9];

        float* op = out_pairs + (size_t)batch * 10;
        op[sub] = pv;
        if (sub < 2) {
            op[8 + sub] = pv2;
        }
        if (sub == 0) {
            out_vol[batch] = vol2;
        }

        // rotate prefetched tile into place (register rename, no data movement)
        if (has_next) {
#pragma unroll
            for (int i = 0; i < 5; i++) {
#pragma unroll
                for (int c = 0; c < 4; c++) {
                    v[i][c] = vn[i][c];
                }
            }
        }
    }
}

extern "C" void kernel_launch(void* const* d_in, const int* in_sizes, int n_in,
                              void* d_out, int out_size) {
    const float* verts = (const float*)d_in[0];
    const int B = in_sizes[0] / 640;   // (B, 5, 128) float32

    float* out = (float*)d_out;
    float* out_pairs = out;                      // (B, 10) flattened first
    float* out_vol   = out + (size_t)B * 10;     // (B,) concatenated after

    const int nquads = (B + 3) / 4;
    const int warps_per_block = 8;               // 256 threads
    // Persistent-ish grid: ~2 CTAs per SM on GB300 (152 SMs), capped by work.
    int blocks = 304;
    const int max_blocks = (nquads + warps_per_block - 1) / warps_per_block;
    if (blocks > max_blocks) blocks = max_blocks;
    cm_validator_kernel<<<blocks, 256>>>(verts, out_pairs, out_vol, B);
}

// round 9
// speedup vs baseline: 1.5637x; 1.5637x over previous
#include <cuda_runtime.h>
#include <cuda_bf16.h>
#include <cstdint>

#define FULL_MASK 0xFFFFFFFFu

// gram index for (i,j), i<=j, nv=5 -> linear index in s[15]
__device__ __forceinline__ constexpr int sidx(int i, int j) {
    return (i == 0 ? 0 : i == 1 ? 5 : i == 2 ? 9 : i == 3 ? 12 : 14) + (j - i);
}

// pair index for (i,j), i<j, nv=5 -> 0..9 in reference order
__device__ __forceinline__ constexpr int pidx(int i, int j) {
    return (i == 0 ? 0 : i == 1 ? 3 : i == 2 ? 5 : 6) + (j - 1);
}

constexpr int WPB = 2;           // warps per block
constexpr int TILE_F4 = 640;     // 4 batches x 160 float4 = 10 KB

template <int N>
__device__ __forceinline__ void cp_wait() {
    asm volatile("cp.async.wait_group %0;" :: "n"(N) : "memory");
}

// Issue the 20 cp.async (16B each) covering one 10KB quad tile, then commit.
__device__ __forceinline__ void prefetch_tile(float4* sdst,
                                              const float4* __restrict__ gsrc,
                                              int lane) {
    uint32_t sbase = (uint32_t)__cvta_generic_to_shared(sdst + lane);
#pragma unroll
    for (int k = 0; k < 20; k++) {
        asm volatile("cp.async.cg.shared.global [%0], [%1], 16;"
                     :: "r"(sbase + (uint32_t)(k * 32 * 16)),
                        "l"(gsrc + lane + 32 * k)
                     : "memory");
    }
    asm volatile("cp.async.commit_group;" ::: "memory");
}

// Full per-quad math + stores. Called by a full warp; shuffles reduce within
// 8-lane groups. Stores guarded by batch < B.
__device__ __forceinline__ void compute_and_store(const float4 v[5][4],
                                                  int batch, int sub,
                                                  float* __restrict__ out_pairs,
                                                  float* __restrict__ out_vol,
                                                  int B) {
    // 15 partial dot products over this lane's 16 dims.
    float s[15];
    {
        int t = 0;
#pragma unroll
        for (int i = 0; i < 5; i++) {
#pragma unroll
            for (int j = i; j < 5; j++) {
                float acc = v[i][0].x * v[j][0].x;
#pragma unroll
                for (int c = 0; c < 4; c++) {
                    if (c > 0) acc = fmaf(v[i][c].x, v[j][c].x, acc);
                    acc = fmaf(v[i][c].y, v[j][c].y, acc);
                    acc = fmaf(v[i][c].z, v[j][c].z, acc);
                    acc = fmaf(v[i][c].w, v[j][c].w, acc);
                }
                s[t++] = acc;
            }
        }
    }

    // Butterfly all-reduce within each 8-lane group: 3 rounds x 15 shfl.
#pragma unroll
    for (int m = 4; m > 0; m >>= 1) {
#pragma unroll
        for (int p = 0; p < 15; p++) {
            s[p] += __shfl_xor_sync(FULL_MASK, s[p], m);
        }
    }

    float nrm[5] = {s[sidx(0,0)], s[sidx(1,1)], s[sidx(2,2)],
                    s[sidx(3,3)], s[sidx(4,4)]};

    float d2[10];
#pragma unroll
    for (int i = 0; i < 5; i++) {
#pragma unroll
        for (int j = i + 1; j < 5; j++) {
            const float g = s[sidx(i, j)];
            d2[pidx(i, j)] = fmaxf(fmaf(-2.0f, g, nrm[i] + nrm[j]), 0.0f);
        }
    }

    // Cayley-Menger det reduced exactly (two unit-pivot eliminations) to a
    // symmetric 4x4: vol2 = det(P) / 9216.
    const float p00 = -2.0f * d2[pidx(0,1)];
    const float p11 = -2.0f * d2[pidx(0,2)];
    const float p22 = -2.0f * d2[pidx(0,3)];
    const float p33 = -2.0f * d2[pidx(0,4)];
    const float p01 = d2[pidx(1,2)] - d2[pidx(0,2)] - d2[pidx(0,1)];
    const float p02 = d2[pidx(1,3)] - d2[pidx(0,3)] - d2[pidx(0,1)];
    const float p03 = d2[pidx(1,4)] - d2[pidx(0,4)] - d2[pidx(0,1)];
    const float p12 = d2[pidx(2,3)] - d2[pidx(0,3)] - d2[pidx(0,2)];
    const float p13 = d2[pidx(2,4)] - d2[pidx(0,4)] - d2[pidx(0,2)];
    const float p23 = d2[pidx(3,4)] - d2[pidx(0,4)] - d2[pidx(0,3)];

    const float s0 = p00 * p11 - p01 * p01;
    const float s1 = p00 * p12 - p02 * p01;
    const float s2 = p00 * p13 - p03 * p01;
    const float s3 = p01 * p12 - p02 * p11;
    const float s4 = p01 * p13 - p03 * p11;
    const float s5 = p02 * p13 - p03 * p12;

    const float c1 = p02 * p23 - p22 * p03;
    const float c2 = p02 * p33 - p23 * p03;
    const float c3 = p12 * p23 - p22 * p13;
    const float c4 = p12 * p33 - p23 * p13;
    const float c5 = p22 * p33 - p23 * p23;

    const float det4 = s0 * c5 - s1 * c4 + s2 * c3 + s3 * c2 - s4 * c1 + s5 * s5;
    const float vol2 = det4 * (1.0f / 9216.0f);

    // Outputs: lanes sub=0..7 own pairs 0..7; sub=0,1 also write pairs 8,9.
    float pv = d2[0];
    pv = (sub == 1) ? d2[1] : pv;
    pv = (sub == 2) ? d2[2] : pv;
    pv = (sub == 3) ? d2[3] : pv;
    pv = (sub == 4) ? d2[4] : pv;
    pv = (sub == 5) ? d2[5] : pv;
    pv = (sub == 6) ? d2[6] : pv;
    pv = (sub == 7) ? d2[7] : pv;
    const float pv2 = (sub == 0) ? d2[8] : d2[9];

    if (batch < B) {
        float* op = out_pairs + (size_t)batch * 10;
        op[sub] = pv;
        if (sub < 2) {
            op[8 + sub] = pv2;
        }
        if (sub == 0) {
            out_vol[batch] = vol2;
        }
    }
}

__global__ void __launch_bounds__(WPB * 32)
cm_validator_kernel(const float* __restrict__ verts,
                    float* __restrict__ out_pairs,   // (B, 10)
                    float* __restrict__ out_vol,     // (B,)
                    int B)
{
    __shared__ float4 buf[WPB][2][TILE_F4];   // 40 KB static

    const int w    = threadIdx.x >> 5;
    const int lane = threadIdx.x & 31;
    const int grp  = lane >> 3;        // 4 batches per quad
    const int sub  = lane & 7;         // 8 lanes x 16 dims per batch

    const int nwarps = gridDim.x * WPB;
    const int warp   = blockIdx.x * WPB + w;

    const int nq_main = B >> 2;        // full quads handled via cp.async
    const float4* base = reinterpret_cast<const float4*>(verts);

    int cur = 0;
    if (warp < nq_main) {
        prefetch_tile(buf[w][0], base + (size_t)warp * TILE_F4, lane);
    }

    for (int quad = warp; quad < nq_main; quad += nwarps) {
        const int nextq = quad + nwarps;
        if (nextq < nq_main) {
            prefetch_tile(buf[w][cur ^ 1], base + (size_t)nextq * TILE_F4, lane);
            cp_wait<1>();
        } else {
            cp_wait<0>();
        }
        __syncwarp();   // make staged tile visible warp-wide

        float4 v[5][4];
        const float4* t = &buf[w][cur][grp * 160 + sub];
#pragma unroll
        for (int i = 0; i < 5; i++) {
#pragma unroll
            for (int c = 0; c < 4; c++) {
                v[i][c] = t[i * 32 + c * 8];
            }
        }
        __syncwarp();   // all lanes done reading buf[cur]; safe to refill next iter

        compute_and_store(v, quad * 4 + grp, sub, out_pairs, out_vol, B);
        cur ^= 1;
    }

    // Tail: B % 4 leftover batches (never taken for B % 4 == 0); warp 0 only.
    if ((B & 3) && warp == 0) {
        const int batch = nq_main * 4 + grp;
        const int batch_c = batch < B ? batch : B - 1;   // clamp loads in-bounds
        const float4* vp = base + (size_t)batch_c * 160 + sub;
        float4 v[5][4];
#pragma unroll
        for (int i = 0; i < 5; i++) {
#pragma unroll
            for (int c = 0; c < 4; c++) {
                v[i][c] = __ldcs(vp + i * 32 + c * 8);
            }
        }
        compute_and_store(v, batch, sub, out_pairs, out_vol, B);
    }
}

extern "C" void kernel_launch(void* const* d_in, const int* in_sizes, int n_in,
                              void* d_out, int out_size) {
    const float* verts = (const float*)d_in[0];
    const int B = in_sizes[0] / 640;   // (B, 5, 128) float32

    float* out = (float*)d_out;
    float* out_pairs = out;                      // (B, 10) flattened first
    float* out_vol   = out + (size_t)B * 10;     // (B,) concatenated after

    // Persistent grid: ~5 blocks/SM (smem-limited at 40KB/block) on 152 SMs.
    const int nquads = (B + 3) / 4;
    int blocks = 760;
    const int max_blocks = (nquads + WPB - 1) / WPB;
    if (blocks > max_blocks) blocks = max_blocks;
    cm_validator_kernel<<<blocks, WPB * 32>>>(verts, out_pairs, out_vol, B);
}

// round 11
// speedup vs baseline: 1.7225x; 1.1016x over previous
#include <cuda_runtime.h>
#include <cuda_bf16.h>

#define FULL_MASK 0xFFFFFFFFu

// gram index for (i,j), i<=j, nv=5 -> linear index in s[15]
__device__ __forceinline__ constexpr int sidx(int i, int j) {
    return (i == 0 ? 0 : i == 1 ? 5 : i == 2 ? 9 : i == 3 ? 12 : 14) + (j - i);
}

// pair index for (i,j), i<j, nv=5 -> 0..9 in reference order
__device__ __forceinline__ constexpr int pidx(int i, int j) {
    return (i == 0 ? 0 : i == 1 ? 3 : i == 2 ? 5 : 6) + (j - 1);
}

__global__ void __launch_bounds__(128, 5)
cm_validator_kernel(const float* __restrict__ verts,
                    float* __restrict__ out_pairs,   // (B, 10)
                    float* __restrict__ out_vol,     // (B,)
                    int B)
{
    const int warp = blockIdx.x * (blockDim.x >> 5) + (threadIdx.x >> 5);
    const int lane = threadIdx.x & 31;
    const int grp  = lane >> 3;        // 4 batches per warp
    const int sub  = lane & 7;         // 8 lanes x 16 dims per batch
    const int batch = warp * 4 + grp;
    if (batch >= B) return;

    // Batch layout: 5 vertices x 128 floats contiguous = 160 float4.
    // Lane covers float4 chunks {sub + 8c : c=0..3} of each vertex row, so
    // for each (vertex, chunk) the 8 lanes of a group touch one contiguous
    // 128B segment. All 20 loads are front-batched (MLP_p1 = 20).
    const float4* vp = reinterpret_cast<const float4*>(verts)
                       + (size_t)batch * 160 + sub;

    float4 v[5][4];
#pragma unroll
    for (int i = 0; i < 5; i++) {
#pragma unroll
        for (int c = 0; c < 4; c++) {
            v[i][c] = __ldcs(vp + i * 32 + c * 8);
        }
    }

    // 15 partial dot products (i<=j) over this lane's 16 dims.
    float s[15];
    {
        int t = 0;
#pragma unroll
        for (int i = 0; i < 5; i++) {
#pragma unroll
            for (int j = i; j < 5; j++) {
                float acc = v[i][0].x * v[j][0].x;
#pragma unroll
                for (int c = 0; c < 4; c++) {
                    if (c > 0) acc = fmaf(v[i][c].x, v[j][c].x, acc);
                    acc = fmaf(v[i][c].y, v[j][c].y, acc);
                    acc = fmaf(v[i][c].z, v[j][c].z, acc);
                    acc = fmaf(v[i][c].w, v[j][c].w, acc);
                }
                s[t++] = acc;
            }
        }
    }

    // Butterfly all-reduce within each 8-lane group: 3 rounds x 15 shfl.
#pragma unroll
    for (int m = 4; m > 0; m >>= 1) {
#pragma unroll
        for (int p = 0; p < 15; p++) {
            s[p] += __shfl_xor_sync(FULL_MASK, s[p], m);
        }
    }

    // Squared distances for the 10 pairs (upper triangle), reference order.
    float nrm[5] = {s[sidx(0,0)], s[sidx(1,1)], s[sidx(2,2)],
                    s[sidx(3,3)], s[sidx(4,4)]};

    float d2[10];
#pragma unroll
    for (int i = 0; i < 5; i++) {
#pragma unroll
        for (int j = i + 1; j < 5; j++) {
            const float g = s[sidx(i, j)];
            d2[pidx(i, j)] = fmaxf(fmaf(-2.0f, g, nrm[i] + nrm[j]), 0.0f);
        }
    }

    // Cayley-Menger determinant reduced exactly (two unit-pivot eliminations)
    // to a symmetric 4x4:  P[a][b] = D[a+1][b+1] - D[0][b+1] - D[0][a+1]
    // vol2 = PREFACTOR * det(CM) = det(P) / 9216.
    const float p00 = -2.0f * d2[pidx(0,1)];
    const float p11 = -2.0f * d2[pidx(0,2)];
    const float p22 = -2.0f * d2[pidx(0,3)];
    const float p33 = -2.0f * d2[pidx(0,4)];
    const float p01 = d2[pidx(1,2)] - d2[pidx(0,2)] - d2[pidx(0,1)];
    const float p02 = d2[pidx(1,3)] - d2[pidx(0,3)] - d2[pidx(0,1)];
    const float p03 = d2[pidx(1,4)] - d2[pidx(0,4)] - d2[pidx(0,1)];
    const float p12 = d2[pidx(2,3)] - d2[pidx(0,3)] - d2[pidx(0,2)];
    const float p13 = d2[pidx(2,4)] - d2[pidx(0,4)] - d2[pidx(0,2)];
    const float p23 = d2[pidx(3,4)] - d2[pidx(0,4)] - d2[pidx(0,3)];

    // det of symmetric 4x4 via 2x2 minors (rows 0,1 vs rows 2,3); c0 == s5.
    const float s0 = p00 * p11 - p01 * p01;
    const float s1 = p00 * p12 - p02 * p01;
    const float s2 = p00 * p13 - p03 * p01;
    const float s3 = p01 * p12 - p02 * p11;
    const float s4 = p01 * p13 - p03 * p11;
    const float s5 = p02 * p13 - p03 * p12;

    const float c1 = p02 * p23 - p22 * p03;
    const float c2 = p02 * p33 - p23 * p03;
    const float c3 = p12 * p23 - p22 * p13;
    const float c4 = p12 * p33 - p23 * p13;
    const float c5 = p22 * p33 - p23 * p23;

    const float det4 = s0 * c5 - s1 * c4 + s2 * c3 + s3 * c2 - s4 * c1 + s5 * s5;
    const float vol2 = det4 * (1.0f / 9216.0f);

    // Select this lane's pair value (lanes sub=0..7 own pairs 0..7; the
    // remaining two pairs are written by sub=0,1 at offset +8).
    float pv = d2[0];
    pv = (sub == 1) ? d2[1] : pv;
    pv = (sub == 2) ? d2[2] : pv;
    pv = (sub == 3) ? d2[3] : pv;
    pv = (sub == 4) ? d2[4] : pv;
    pv = (sub == 5) ? d2[5] : pv;
    pv = (sub == 6) ? d2[6] : pv;
    pv = (sub == 7) ? d2[7] : pv;
    float pv2 = (sub == 0) ? d2[8] : d2[9];

    float* op = out_pairs + (size_t)batch * 10;
    op[sub] = pv;
    if (sub < 2) {
        op[8 + sub] = pv2;
    }
    if (sub == 0) {
        out_vol[batch] = vol2;
    }
}

extern "C" void kernel_launch(void* const* d_in, const int* in_sizes, int n_in,
                              void* d_out, int out_size) {
    const float* verts = (const float*)d_in[0];
    const int B = in_sizes[0] / 640;   // (B, 5, 128) float32

    float* out = (float*)d_out;
    float* out_pairs = out;                      // (B, 10) flattened first
    float* out_vol   = out + (size_t)B * 10;     // (B,) concatenated after

    const int warps_needed = (B + 3) / 4;        // 4 batches per warp
    const int warps_per_block = 4;               // 128 threads
    const int blocks = (warps_needed + warps_per_block - 1) / warps_per_block;
    cm_validator_kernel<<<blocks, 128>>>(verts, out_pairs, out_vol, B);
}